// round 13
// baseline (speedup 1.0000x reference)
#include <cuda_runtime.h>
#include <cstdint>

// ATSS: B=16, N=30000, G=64, K=9. Single fused kernel, cell-binned compaction,
// per-image load-polling barriers.
// Out (float), tuple order, each [B,G,K], S=9216:
//   [0,S) pred_idx | [S,2S) gt_idx | [2S,3S) mask | [3S,4S) ious

#define B_ 16
#define N_ 30000
#define G_ 64
#define KK 9
#define FULL 0xffffffffu
#define CAP 256
#define NBLK 256
#define NTHR 512
#define SLICE (N_ / 16)        // 1875 preds per block slice

// Radius pre-filter (uniform data: 9th-NN ~0.0098; r=0.04 -> ~150 cands/GT).
// Correctness never depends on it: certificate + inline exact fallback.
#define RADIUS 0.04f
#define R2G   (RADIUS * RADIUS * 1.000002f)
#define R2CHK (RADIUS * RADIUS * 0.999998f)
// Cell mask dilation: must exceed RADIUS + all fp fuzz (0.045 >> 0.04+1e-6).
#define RCELL 0.045f

__device__ int      d_cnt[B_ * G_];        // zeroed at load; self-reset each call
__device__ float4   d_rec[B_ * G_ * CAP];  // (cx, cy, bitcast idx, -)
__device__ unsigned g_arrive[B_];          // per-image arrivals (self-reset)
__device__ unsigned g_rel[B_];             // per-image release flag (monotone)

__device__ __forceinline__ float f_inf() { return __int_as_float(0x7f800000); }

// Lane-distributed sorted top-9 insertion (exact fallback path only).
__device__ __forceinline__ void insert_batch(
    float de, int idx, bool v, float& ldv, int& liv, int lane)
{
    float d8 = __shfl_sync(FULL, ldv, 8);
    int   i8 = __shfl_sync(FULL, liv, 8);
    bool qq = v && ((de < d8) || (de == d8 && idx < i8));
    unsigned m = __ballot_sync(FULL, qq);
    while (m) {
        int src = __ffs(m) - 1; m &= m - 1;
        float dv = __shfl_sync(FULL, de, src);
        int   iv = __shfl_sync(FULL, idx, src);
        bool ogt = (ldv > dv) || (ldv == dv && liv > iv);
        unsigned bgt = __ballot_sync(FULL, ogt);
        int pos = __popc(~bgt & 0x1FFu);
        float pd = __shfl_up_sync(FULL, ldv, 1);
        int   pi2 = __shfl_up_sync(FULL, liv, 1);
        if (lane <= 8) {
            if (lane == pos)     { ldv = dv; liv = iv; }
            else if (lane > pos) { ldv = pd; liv = pi2; }
        }
    }
}

#define CE(a, b)                                                            \
    { bool sw = (ed[a] > ed[b]) || (ed[a] == ed[b] && ei[a] > ei[b]);       \
      float td = sw ? ed[b] : ed[a]; ed[b] = sw ? ed[a] : ed[b]; ed[a] = td;\
      int   ti = sw ? ei[b] : ei[a]; ei[b] = sw ? ei[a] : ei[b]; ei[a] = ti; }

__global__ __launch_bounds__(NTHR) void atss_fused(
    const float* __restrict__ pred, const float* __restrict__ gt,
    float* __restrict__ out)
{
    // ====== Phase 0: per-image 8x8 cell -> GT bitmask (redundant per block) ======
    const int img   = blockIdx.x >> 4;
    const int slice = blockIdx.x & 15;

    __shared__ float2 sg[G_];
    __shared__ unsigned long long smask[64];
    if (threadIdx.x < 64) smask[threadIdx.x] = 0ull;
    __syncthreads();
    if (threadIdx.x < G_) {
        float4 q = reinterpret_cast<const float4*>(gt)[img * G_ + threadIdx.x];
        sg[threadIdx.x] = make_float2(q.x, q.y);
        int x0 = max(0, (int)floorf((q.x - RCELL) * 8.0f));
        int x1 = min(7, (int)floorf((q.x + RCELL) * 8.0f));
        int y0 = max(0, (int)floorf((q.y - RCELL) * 8.0f));
        int y1 = min(7, (int)floorf((q.y + RCELL) * 8.0f));
        unsigned long long bit = 1ull << threadIdx.x;
        for (int cy = y0; cy <= y1; cy++)
            for (int cx = x0; cx <= x1; cx++)
                atomicOr(&smask[cy * 8 + cx], bit);
    }
    __syncthreads();

    // ================= Phase A: cell-binned candidate compaction =================
    {
        const float4* __restrict__ pb =
            reinterpret_cast<const float4*>(pred) + (size_t)img * N_;
        const int sbeg = slice * SLICE;
        const int send = sbeg + SLICE;

        for (int i = sbeg + (int)threadIdx.x; i < send; i += NTHR) {
            float4 p = pb[i];
            int cx = min(7, max(0, (int)(p.x * 8.0f)));
            int cy = min(7, max(0, (int)(p.y * 8.0f)));
            unsigned long long m = smask[cy * 8 + cx];
            while (m) {
                int g = __ffsll((long long)m) - 1; m &= m - 1;
                float2 gg = sg[g];
                float dx = gg.x - p.x, dy = gg.y - p.y;
                if (__fmaf_rn(dx, dx, dy * dy) <= R2G) {
                    int pos = atomicAdd(&d_cnt[img * G_ + g], 1);
                    if (pos < CAP)
                        d_rec[(img * G_ + g) * CAP + pos] =
                            make_float4(p.x, p.y, __int_as_float(i), 0.0f);
                }
            }
        }
    }

    // ============ Per-image barrier (16 blocks; load-polling, replay-safe) ======
    __threadfence();
    __syncthreads();
    if (threadIdx.x == 0) {
        volatile unsigned* rel = &g_rel[img];
        unsigned ph = *rel;                       // snapshot BEFORE arriving
        unsigned old = atomicAdd(&g_arrive[img], 1u);
        if (old == 15u) {
            g_arrive[img] = 0u;                   // reset for next replay
            __threadfence();
            atomicAdd(&g_rel[img], 1u);           // release (monotone)
        } else {
            while (*rel == ph) __nanosleep(128);  // plain-load polling
        }
    }
    __syncthreads();
    __threadfence();

    // ================= Phase B: per-GT top-9 + epilogue =================
    const int wid  = threadIdx.x >> 5;
    const int lane = threadIdx.x & 31;
    const int wgl  = (blockIdx.x << 4) + wid;    // 0..4095
    if ((wgl & 3) != 0) return;                  // 1024 active warps
    const int gti = wgl >> 2;                    // 0..1023 (same image as Phase A)
    const int bimg = gti >> 6;
    const int g    = gti & 63;

    const float4* __restrict__ pb  = reinterpret_cast<const float4*>(pred) + (size_t)bimg * N_;
    const float2* __restrict__ pb2 = reinterpret_cast<const float2*>(pred) + (size_t)bimg * N_ * 2;
    float4 qg = reinterpret_cast<const float4*>(gt)[bimg * G_ + g];

    int c = __ldcg(&d_cnt[bimg * G_ + g]);
    if (lane == 0) d_cnt[bimg * G_ + g] = 0;     // self-reset for graph replay
    const float4* __restrict__ rec = &d_rec[(bimg * G_ + g) * CAP];

    int myidx = 0x7fffffff;
    bool ok = (c >= KK && c <= CAP);
    if (ok) {
        float ed[8]; int ei[8];
#pragma unroll
        for (int q = 0; q < 8; q++) {
            int k = lane + q * 32;
            bool v = k < c;
            float4 r = rec[v ? k : 0];
            // Exact distance matching JAX: rn sub/mul/add then IEEE sqrt.
            float dx = __fsub_rn(qg.x, r.x), dy = __fsub_rn(qg.y, r.y);
            float de = __fsqrt_rn(__fadd_rn(__fmul_rn(dx, dx), __fmul_rn(dy, dy)));
            ed[q] = v ? de : f_inf();
            ei[q] = v ? __float_as_int(r.z) : 0x7fffffff;
        }
        // Batcher 8-sorter (19 CEs, static indices, asc by (d, idx)).
        CE(0,1) CE(2,3) CE(4,5) CE(6,7)
        CE(0,2) CE(1,3) CE(4,6) CE(5,7)
        CE(1,2) CE(5,6)
        CE(0,4) CE(1,5) CE(2,6) CE(3,7)
        CE(2,4) CE(3,5)
        CE(1,2) CE(3,4) CE(5,6)

        // 9 selection rounds via hardware REDUX (d>=0 -> uint-monotone).
        unsigned lastd = 0; int lasti = 0x7fffffff;
        for (int r = 0; r < KK; r++) {
            unsigned db = __float_as_uint(ed[0]);
            unsigned mn = __reduce_min_sync(FULL, db);
            bool match = (db == mn);
            unsigned imn = __reduce_min_sync(FULL, match ? (unsigned)ei[0] : 0x7fffffffu);
            if (lane == r) myidx = (int)imn;
            lastd = mn; lasti = (int)imn;
            bool win = match && ((unsigned)ei[0] == imn);
            if (win) {
#pragma unroll
                for (int q = 0; q < 7; q++) { ed[q] = ed[q + 1]; ei[q] = ei[q + 1]; }
                ed[7] = f_inf(); ei[7] = 0x7fffffff;
            }
        }
        float d8 = __uint_as_float(lastd);
        // Certificate: cell-excluded preds have d > RCELL-fuzz, radius-excluded
        // have d^2 > R2CHK; strictly-inside 9th => candidate top-9 == exact top-9.
        ok = (lasti != 0x7fffffff) && (__fmul_rn(d8, d8) < R2CHK);
    }
    if (!ok) {   // exact full scan (deterministic, identical arithmetic)
        float ldv = f_inf(); int liv = 0x7fffffff;
        for (int b = 0; b < N_; b += 32) {
            int idx = b + lane; bool v = idx < N_;
            float2 p = pb2[2 * (v ? idx : 0)];
            float dx = __fsub_rn(qg.x, p.x), dy = __fsub_rn(qg.y, p.y);
            float de = __fsqrt_rn(__fadd_rn(__fmul_rn(dx, dx), __fmul_rn(dy, dy)));
            insert_batch(de, idx, v, ldv, liv, lane);
        }
        myidx = liv;   // lanes 0..8 hold ranks 0..8
    }

    // ---- epilogue: lanes 0..8 in parallel, exact rn ops ----
    float ghw = __fmul_rn(0.5f, qg.z), ghh = __fmul_rn(0.5f, qg.w);
    float gx1 = __fsub_rn(qg.x, ghw), gy1 = __fsub_rn(qg.y, ghh);
    float gx2 = __fadd_rn(qg.x, ghw), gy2 = __fadd_rn(qg.y, ghh);
    float area_g = __fmul_rn(__fsub_rn(gx2, gx1), __fsub_rn(gy2, gy1));

    float iou = 0.0f, pcx = 0.0f, pcy = 0.0f;
    if (lane < KK) {
        float4 p = pb[myidx];
        pcx = p.x; pcy = p.y;
        float hw = __fmul_rn(0.5f, p.z), hh = __fmul_rn(0.5f, p.w);
        float bx1 = __fsub_rn(p.x, hw), by1 = __fsub_rn(p.y, hh);
        float bx2 = __fadd_rn(p.x, hw), by2 = __fadd_rn(p.y, hh);
        float ltx = fmaxf(gx1, bx1), lty = fmaxf(gy1, by1);
        float rbx = fminf(gx2, bx2), rby = fminf(gy2, by2);
        float wd = fmaxf(__fsub_rn(rbx, ltx), 0.0f);
        float ht = fmaxf(__fsub_rn(rby, lty), 0.0f);
        float inter = __fmul_rn(wd, ht);
        float area_b = __fmul_rn(__fsub_rn(bx2, bx1), __fsub_rn(by2, by1));
        float den = __fsub_rn(__fadd_rn(area_g, area_b), inter);
        iou = __fdiv_rn(inter, den);
    }
    float iouk[KK];
#pragma unroll
    for (int k = 0; k < KK; k++) iouk[k] = __shfl_sync(FULL, iou, k);
    float s = 0.0f;
#pragma unroll
    for (int k = 0; k < KK; k++) s = __fadd_rn(s, iouk[k]);
    float mean = __fdiv_rn(s, 9.0f);
    float vv = 0.0f;
#pragma unroll
    for (int k = 0; k < KK; k++) {
        float cdev = __fsub_rn(iouk[k], mean);
        vv = __fadd_rn(vv, __fmul_rn(cdev, cdev));
    }
    float thr = __fadd_rn(mean, __fsqrt_rn(__fdiv_rn(vv, 8.0f)));

    if (lane < KK) {
        bool inside = (gx1 <= pcx) && (pcx <= gx2) && (gy1 <= pcy) && (pcy <= gy2);
        bool msk = (iou >= thr) && inside;
        const size_t S = (size_t)B_ * G_ * KK;
        const size_t base = ((size_t)bimg * G_ + g) * KK + lane;
        out[base]         = msk ? (float)myidx : -1.0f;
        out[S + base]     = msk ? (float)g : -1.0f;
        out[2 * S + base] = msk ? 1.0f : 0.0f;
        out[3 * S + base] = iou;
    }
}

extern "C" void kernel_launch(void* const* d_in, const int* in_sizes, int n_in,
                              void* d_out, int out_size) {
    const float* pred = (const float*)d_in[0];  // [16,30000,4]
    const float* gt   = (const float*)d_in[1];  // [16,64,4]
    float* out = (float*)d_out;
    atss_fused<<<NBLK, NTHR>>>(pred, gt, out);
}

// round 14
// speedup vs baseline: 1.6800x; 1.6800x over previous
#include <cuda_runtime.h>
#include <cstdint>

// ATSS: B=16, N=30000, G=64, K=9. Two kernels:
//   1) cell-binned candidate compaction (8x8 GT-occupancy bitmask)
//   2) per-GT top-9 + epilogue (proven R6 assign)
// Out (float), tuple order, each [B,G,K], S=9216:
//   [0,S) pred_idx | [S,2S) gt_idx | [2S,3S) mask | [3S,4S) ious

#define B_ 16
#define N_ 30000
#define G_ 64
#define KK 9
#define FULL 0xffffffffu
#define CAP 256
#define NTHR 512
#define SLICE (N_ / 16)        // 1875 preds per compact block

// Radius pre-filter (uniform data: 9th-NN ~0.0098; r=0.04 -> ~150 cands/GT).
// Correctness never depends on it: certificate + inline exact fallback.
#define RADIUS 0.04f
#define R2G   (RADIUS * RADIUS * 1.000002f)
#define R2CHK (RADIUS * RADIUS * 0.999998f)
// Cell mask dilation: must exceed RADIUS + all fp fuzz (0.045 >> 0.04+1e-6).
#define RCELL 0.045f

__device__ int    d_cnt[B_ * G_];          // zeroed at load; self-reset each call
__device__ float4 d_rec[B_ * G_ * CAP];    // (cx, cy, bitcast idx, -)

__device__ __forceinline__ float f_inf() { return __int_as_float(0x7f800000); }

// ---------------- Kernel 1: cell-binned candidate compaction ----------------
__global__ __launch_bounds__(NTHR) void atss_compact(
    const float* __restrict__ pred, const float* __restrict__ gt)
{
    const int img   = blockIdx.x >> 4;
    const int slice = blockIdx.x & 15;

    // Per-image 8x8 cell -> GT bitmask (built redundantly per block in smem).
    __shared__ float2 sg[G_];
    __shared__ unsigned long long smask[64];
    if (threadIdx.x < 64) smask[threadIdx.x] = 0ull;
    __syncthreads();
    if (threadIdx.x < G_) {
        float4 q = reinterpret_cast<const float4*>(gt)[img * G_ + threadIdx.x];
        sg[threadIdx.x] = make_float2(q.x, q.y);
        int x0 = max(0, (int)floorf((q.x - RCELL) * 8.0f));
        int x1 = min(7, (int)floorf((q.x + RCELL) * 8.0f));
        int y0 = max(0, (int)floorf((q.y - RCELL) * 8.0f));
        int y1 = min(7, (int)floorf((q.y + RCELL) * 8.0f));
        unsigned long long bit = 1ull << threadIdx.x;
        for (int cy = y0; cy <= y1; cy++)
            for (int cx = x0; cx <= x1; cx++)
                atomicOr(&smask[cy * 8 + cx], bit);
    }
    __syncthreads();

    const float4* __restrict__ pb =
        reinterpret_cast<const float4*>(pred) + (size_t)img * N_;
    const int sbeg = slice * SLICE;
    const int send = sbeg + SLICE;

    for (int i = sbeg + (int)threadIdx.x; i < send; i += NTHR) {
        float4 p = pb[i];
        int cx = min(7, max(0, (int)(p.x * 8.0f)));
        int cy = min(7, max(0, (int)(p.y * 8.0f)));
        unsigned long long m = smask[cy * 8 + cx];
        while (m) {
            int g = __ffsll((long long)m) - 1; m &= m - 1;
            float2 gg = sg[g];
            float dx = gg.x - p.x, dy = gg.y - p.y;
            if (__fmaf_rn(dx, dx, dy * dy) <= R2G) {
                int pos = atomicAdd(&d_cnt[img * G_ + g], 1);
                if (pos < CAP)
                    d_rec[(img * G_ + g) * CAP + pos] =
                        make_float4(p.x, p.y, __int_as_float(i), 0.0f);
            }
        }
    }
}

// Lane-distributed sorted top-9 insertion (exact fallback path only).
__device__ __forceinline__ void insert_batch(
    float de, int idx, bool v, float& ldv, int& liv, int lane)
{
    float d8 = __shfl_sync(FULL, ldv, 8);
    int   i8 = __shfl_sync(FULL, liv, 8);
    bool qq = v && ((de < d8) || (de == d8 && idx < i8));
    unsigned m = __ballot_sync(FULL, qq);
    while (m) {
        int src = __ffs(m) - 1; m &= m - 1;
        float dv = __shfl_sync(FULL, de, src);
        int   iv = __shfl_sync(FULL, idx, src);
        bool ogt = (ldv > dv) || (ldv == dv && liv > iv);
        unsigned bgt = __ballot_sync(FULL, ogt);
        int pos = __popc(~bgt & 0x1FFu);
        float pd = __shfl_up_sync(FULL, ldv, 1);
        int   pi2 = __shfl_up_sync(FULL, liv, 1);
        if (lane <= 8) {
            if (lane == pos)     { ldv = dv; liv = iv; }
            else if (lane > pos) { ldv = pd; liv = pi2; }
        }
    }
}

#define CE(a, b)                                                            \
    { bool sw = (ed[a] > ed[b]) || (ed[a] == ed[b] && ei[a] > ei[b]);       \
      float td = sw ? ed[b] : ed[a]; ed[b] = sw ? ed[a] : ed[b]; ed[a] = td;\
      int   ti = sw ? ei[b] : ei[a]; ei[b] = sw ? ei[a] : ei[b]; ei[a] = ti; }

// ---------------- Kernel 2: per-GT top-9 + epilogue ----------------
__global__ __launch_bounds__(128) void atss_assign(
    const float* __restrict__ pred, const float* __restrict__ gt,
    float* __restrict__ out)
{
    const int warp = (blockIdx.x << 2) + (threadIdx.x >> 5);  // 0..1023
    const int img  = warp >> 6;
    const int g    = warp & 63;
    const int lane = threadIdx.x & 31;

    const float4* __restrict__ pb  = reinterpret_cast<const float4*>(pred) + (size_t)img * N_;
    const float2* __restrict__ pb2 = reinterpret_cast<const float2*>(pred) + (size_t)img * N_ * 2;
    float4 qg = reinterpret_cast<const float4*>(gt)[img * G_ + g];

    int c = d_cnt[img * G_ + g];
    if (lane == 0) d_cnt[img * G_ + g] = 0;      // self-reset for graph replay
    const float4* __restrict__ rec = &d_rec[(img * G_ + g) * CAP];

    int myidx = 0x7fffffff;
    bool ok = (c >= KK && c <= CAP);
    if (ok) {
        // Per-lane <=8 candidates, coalesced LDG.128 streams.
        float ed[8]; int ei[8];
#pragma unroll
        for (int q = 0; q < 8; q++) {
            int k = lane + q * 32;
            bool v = k < c;
            float4 r = rec[v ? k : 0];
            // Exact distance matching JAX: rn sub/mul/add then IEEE sqrt.
            float dx = __fsub_rn(qg.x, r.x), dy = __fsub_rn(qg.y, r.y);
            float de = __fsqrt_rn(__fadd_rn(__fmul_rn(dx, dx), __fmul_rn(dy, dy)));
            ed[q] = v ? de : f_inf();
            ei[q] = v ? __float_as_int(r.z) : 0x7fffffff;
        }
        // Batcher 8-sorter (19 CEs, static indices, asc by (d, idx)).
        CE(0,1) CE(2,3) CE(4,5) CE(6,7)
        CE(0,2) CE(1,3) CE(4,6) CE(5,7)
        CE(1,2) CE(5,6)
        CE(0,4) CE(1,5) CE(2,6) CE(3,7)
        CE(2,4) CE(3,5)
        CE(1,2) CE(3,4) CE(5,6)

        // 9 selection rounds via hardware REDUX (d>=0 -> uint-monotone).
        unsigned lastd = 0; int lasti = 0x7fffffff;
        for (int r = 0; r < KK; r++) {
            unsigned db = __float_as_uint(ed[0]);
            unsigned mn = __reduce_min_sync(FULL, db);
            bool match = (db == mn);
            unsigned imn = __reduce_min_sync(FULL, match ? (unsigned)ei[0] : 0x7fffffffu);
            if (lane == r) myidx = (int)imn;
            lastd = mn; lasti = (int)imn;
            bool win = match && ((unsigned)ei[0] == imn);
            if (win) {
#pragma unroll
                for (int q = 0; q < 7; q++) { ed[q] = ed[q + 1]; ei[q] = ei[q + 1]; }
                ed[7] = f_inf(); ei[7] = 0x7fffffff;
            }
        }
        float d8 = __uint_as_float(lastd);
        // Certificate: cell-excluded preds have d > RCELL-fuzz; radius-excluded
        // have d^2 > R2CHK; strictly-inside 9th => candidate top-9 == exact top-9.
        ok = (lasti != 0x7fffffff) && (__fmul_rn(d8, d8) < R2CHK);
    }
    if (!ok) {   // exact full scan (deterministic, identical arithmetic)
        float ldv = f_inf(); int liv = 0x7fffffff;
        for (int b = 0; b < N_; b += 32) {
            int idx = b + lane; bool v = idx < N_;
            float2 p = pb2[2 * (v ? idx : 0)];
            float dx = __fsub_rn(qg.x, p.x), dy = __fsub_rn(qg.y, p.y);
            float de = __fsqrt_rn(__fadd_rn(__fmul_rn(dx, dx), __fmul_rn(dy, dy)));
            insert_batch(de, idx, v, ldv, liv, lane);
        }
        myidx = liv;   // lanes 0..8 hold ranks 0..8
    }

    // ---- epilogue: lanes 0..8 in parallel, exact rn ops ----
    float ghw = __fmul_rn(0.5f, qg.z), ghh = __fmul_rn(0.5f, qg.w);
    float gx1 = __fsub_rn(qg.x, ghw), gy1 = __fsub_rn(qg.y, ghh);
    float gx2 = __fadd_rn(qg.x, ghw), gy2 = __fadd_rn(qg.y, ghh);
    float area_g = __fmul_rn(__fsub_rn(gx2, gx1), __fsub_rn(gy2, gy1));

    float iou = 0.0f, pcx = 0.0f, pcy = 0.0f;
    if (lane < KK) {
        float4 p = pb[myidx];
        pcx = p.x; pcy = p.y;
        float hw = __fmul_rn(0.5f, p.z), hh = __fmul_rn(0.5f, p.w);
        float bx1 = __fsub_rn(p.x, hw), by1 = __fsub_rn(p.y, hh);
        float bx2 = __fadd_rn(p.x, hw), by2 = __fadd_rn(p.y, hh);
        float ltx = fmaxf(gx1, bx1), lty = fmaxf(gy1, by1);
        float rbx = fminf(gx2, bx2), rby = fminf(gy2, by2);
        float wd = fmaxf(__fsub_rn(rbx, ltx), 0.0f);
        float ht = fmaxf(__fsub_rn(rby, lty), 0.0f);
        float inter = __fmul_rn(wd, ht);
        float area_b = __fmul_rn(__fsub_rn(bx2, bx1), __fsub_rn(by2, by1));
        float den = __fsub_rn(__fadd_rn(area_g, area_b), inter);
        iou = __fdiv_rn(inter, den);
    }
    float iouk[KK];
#pragma unroll
    for (int k = 0; k < KK; k++) iouk[k] = __shfl_sync(FULL, iou, k);
    float s = 0.0f;
#pragma unroll
    for (int k = 0; k < KK; k++) s = __fadd_rn(s, iouk[k]);
    float mean = __fdiv_rn(s, 9.0f);
    float vv = 0.0f;
#pragma unroll
    for (int k = 0; k < KK; k++) {
        float cdev = __fsub_rn(iouk[k], mean);
        vv = __fadd_rn(vv, __fmul_rn(cdev, cdev));
    }
    float thr = __fadd_rn(mean, __fsqrt_rn(__fdiv_rn(vv, 8.0f)));

    if (lane < KK) {
        bool inside = (gx1 <= pcx) && (pcx <= gx2) && (gy1 <= pcy) && (pcy <= gy2);
        bool msk = (iou >= thr) && inside;
        const size_t S = (size_t)B_ * G_ * KK;
        const size_t base = ((size_t)img * G_ + g) * KK + lane;
        out[base]         = msk ? (float)myidx : -1.0f;
        out[S + base]     = msk ? (float)g : -1.0f;
        out[2 * S + base] = msk ? 1.0f : 0.0f;
        out[3 * S + base] = iou;
    }
}

extern "C" void kernel_launch(void* const* d_in, const int* in_sizes, int n_in,
                              void* d_out, int out_size) {
    const float* pred = (const float*)d_in[0];  // [16,30000,4]
    const float* gt   = (const float*)d_in[1];  // [16,64,4]
    float* out = (float*)d_out;
    atss_compact<<<B_ * 16, NTHR>>>(pred, gt);            // 256 blocks
    atss_assign<<<(B_ * G_) / 4, 128>>>(pred, gt, out);   // 256 blocks
}

// round 17
// speedup vs baseline: 1.9791x; 1.1780x over previous
#include <cuda_runtime.h>
#include <cstdint>

// ATSS: B=16, N=30000, G=64, K=9. Two kernels:
//   1) cell-binned candidate compaction (8x8 GT-occupancy bitmask, MLP-4 prefetch)
//   2) per-GT top-9 + epilogue (count-independent record loads)
// Out (float), tuple order, each [B,G,K], S=9216:
//   [0,S) pred_idx | [S,2S) gt_idx | [2S,3S) mask | [3S,4S) ious

#define B_ 16
#define N_ 30000
#define G_ 64
#define KK 9
#define FULL 0xffffffffu
#define CAP 256
#define NTHR 512
#define SLICE (N_ / 16)        // 1875 preds per compact block (<= 4*NTHR)

// Radius pre-filter (uniform data: 9th-NN ~0.0098; r=0.04 -> ~150 cands/GT).
// Correctness never depends on it: certificate + inline exact fallback.
#define RADIUS 0.04f
#define R2G   (RADIUS * RADIUS * 1.000002f)
#define R2CHK (RADIUS * RADIUS * 0.999998f)
// Cell mask dilation: must exceed RADIUS + all fp fuzz (0.045 >> 0.04+1e-6).
#define RCELL 0.045f

__device__ int    d_cnt[B_ * G_];          // zeroed at load; self-reset each call
__device__ float4 d_rec[B_ * G_ * CAP];    // (cx, cy, bitcast idx, -)

__device__ __forceinline__ float f_inf() { return __int_as_float(0x7f800000); }

// ---------------- Kernel 1: cell-binned candidate compaction ----------------
__global__ __launch_bounds__(NTHR) void atss_compact(
    const float* __restrict__ pred, const float* __restrict__ gt)
{
    const int img   = blockIdx.x >> 4;
    const int slice = blockIdx.x & 15;

    // Per-image 8x8 cell -> GT bitmask (built redundantly per block in smem).
    __shared__ float2 sg[G_];
    __shared__ unsigned long long smask[64];
    if (threadIdx.x < 64) smask[threadIdx.x] = 0ull;
    __syncthreads();
    if (threadIdx.x < G_) {
        float4 q = reinterpret_cast<const float4*>(gt)[img * G_ + threadIdx.x];
        sg[threadIdx.x] = make_float2(q.x, q.y);
        int x0 = max(0, (int)floorf((q.x - RCELL) * 8.0f));
        int x1 = min(7, (int)floorf((q.x + RCELL) * 8.0f));
        int y0 = max(0, (int)floorf((q.y - RCELL) * 8.0f));
        int y1 = min(7, (int)floorf((q.y + RCELL) * 8.0f));
        unsigned long long bit = 1ull << threadIdx.x;
        for (int cy = y0; cy <= y1; cy++)
            for (int cx = x0; cx <= x1; cx++)
                atomicOr(&smask[cy * 8 + cx], bit);
    }

    const float4* __restrict__ pb =
        reinterpret_cast<const float4*>(pred) + (size_t)img * N_;
    const int sbeg = slice * SLICE;

    // Prefetch all (<=4) preds for this thread up front: MLP=4, one load wave
    // overlapped with the mask build above.
    float4 p[4]; int ii[4]; bool pv[4];
#pragma unroll
    for (int q = 0; q < 4; q++) {
        int i = sbeg + (int)threadIdx.x + q * NTHR;
        pv[q] = (i < sbeg + SLICE);
        ii[q] = i;
        p[q]  = pb[pv[q] ? i : sbeg];
    }
    __syncthreads();   // smask/sg ready

#pragma unroll
    for (int q = 0; q < 4; q++) {
        if (!pv[q]) continue;
        int cx = min(7, max(0, (int)(p[q].x * 8.0f)));
        int cy = min(7, max(0, (int)(p[q].y * 8.0f)));
        unsigned long long m = smask[cy * 8 + cx];
        while (m) {
            int g = __ffsll((long long)m) - 1; m &= m - 1;
            float2 gg = sg[g];
            float dx = gg.x - p[q].x, dy = gg.y - p[q].y;
            if (__fmaf_rn(dx, dx, dy * dy) <= R2G) {
                int pos = atomicAdd(&d_cnt[img * G_ + g], 1);
                if (pos < CAP)
                    d_rec[(img * G_ + g) * CAP + pos] =
                        make_float4(p[q].x, p[q].y, __int_as_float(ii[q]), 0.0f);
            }
        }
    }
}

// Lane-distributed sorted top-9 insertion (exact fallback path only).
__device__ __forceinline__ void insert_batch(
    float de, int idx, bool v, float& ldv, int& liv, int lane)
{
    float d8 = __shfl_sync(FULL, ldv, 8);
    int   i8 = __shfl_sync(FULL, liv, 8);
    bool qq = v && ((de < d8) || (de == d8 && idx < i8));
    unsigned m = __ballot_sync(FULL, qq);
    while (m) {
        int src = __ffs(m) - 1; m &= m - 1;
        float dv = __shfl_sync(FULL, de, src);
        int   iv = __shfl_sync(FULL, idx, src);
        bool ogt = (ldv > dv) || (ldv == dv && liv > iv);
        unsigned bgt = __ballot_sync(FULL, ogt);
        int pos = __popc(~bgt & 0x1FFu);
        float pd = __shfl_up_sync(FULL, ldv, 1);
        int   pi2 = __shfl_up_sync(FULL, liv, 1);
        if (lane <= 8) {
            if (lane == pos)     { ldv = dv; liv = iv; }
            else if (lane > pos) { ldv = pd; liv = pi2; }
        }
    }
}

#define CE(a, b)                                                            \
    { bool sw = (ed[a] > ed[b]) || (ed[a] == ed[b] && ei[a] > ei[b]);       \
      float td = sw ? ed[b] : ed[a]; ed[b] = sw ? ed[a] : ed[b]; ed[a] = td;\
      int   ti = sw ? ei[b] : ei[a]; ei[b] = sw ? ei[a] : ei[b]; ei[a] = ti; }

// ---------------- Kernel 2: per-GT top-9 + epilogue ----------------
__global__ __launch_bounds__(128) void atss_assign(
    const float* __restrict__ pred, const float* __restrict__ gt,
    float* __restrict__ out)
{
    const int warp = (blockIdx.x << 2) + (threadIdx.x >> 5);  // 0..1023
    const int img  = warp >> 6;
    const int g    = warp & 63;
    const int lane = threadIdx.x & 31;

    const float4* __restrict__ pb  = reinterpret_cast<const float4*>(pred) + (size_t)img * N_;
    const float2* __restrict__ pb2 = reinterpret_cast<const float2*>(pred) + (size_t)img * N_ * 2;
    const float4* __restrict__ rec = &d_rec[(img * G_ + g) * CAP];

    // Issue the count load AND all 8 record loads concurrently (records do not
    // depend on c; slots >= c are masked to +inf below -> deterministic).
    int c = __ldcg(&d_cnt[img * G_ + g]);
    float4 r8[8];
#pragma unroll
    for (int q = 0; q < 8; q++) r8[q] = rec[lane + q * 32];
    float4 qg = reinterpret_cast<const float4*>(gt)[img * G_ + g];
    if (lane == 0) d_cnt[img * G_ + g] = 0;      // self-reset for graph replay

    int myidx = 0x7fffffff;
    bool ok = (c >= KK && c <= CAP);
    if (ok) {
        float ed[8]; int ei[8];
#pragma unroll
        for (int q = 0; q < 8; q++) {
            bool v = (lane + q * 32) < c;
            // Exact distance matching JAX: rn sub/mul/add then IEEE sqrt.
            float dx = __fsub_rn(qg.x, r8[q].x), dy = __fsub_rn(qg.y, r8[q].y);
            float de = __fsqrt_rn(__fadd_rn(__fmul_rn(dx, dx), __fmul_rn(dy, dy)));
            ed[q] = v ? de : f_inf();
            ei[q] = v ? __float_as_int(r8[q].z) : 0x7fffffff;
        }
        // Batcher 8-sorter (19 CEs, static indices, asc by (d, idx)).
        CE(0,1) CE(2,3) CE(4,5) CE(6,7)
        CE(0,2) CE(1,3) CE(4,6) CE(5,7)
        CE(1,2) CE(5,6)
        CE(0,4) CE(1,5) CE(2,6) CE(3,7)
        CE(2,4) CE(3,5)
        CE(1,2) CE(3,4) CE(5,6)

        // 9 selection rounds via hardware REDUX (d>=0 -> uint-monotone).
        unsigned lastd = 0; int lasti = 0x7fffffff;
        for (int r = 0; r < KK; r++) {
            unsigned db = __float_as_uint(ed[0]);
            unsigned mn = __reduce_min_sync(FULL, db);
            bool match = (db == mn);
            unsigned imn = __reduce_min_sync(FULL, match ? (unsigned)ei[0] : 0x7fffffffu);
            if (lane == r) myidx = (int)imn;
            lastd = mn; lasti = (int)imn;
            bool win = match && ((unsigned)ei[0] == imn);
            if (win) {
#pragma unroll
                for (int q = 0; q < 7; q++) { ed[q] = ed[q + 1]; ei[q] = ei[q + 1]; }
                ed[7] = f_inf(); ei[7] = 0x7fffffff;
            }
        }
        float d8 = __uint_as_float(lastd);
        // Certificate: cell-excluded preds have d > RCELL-fuzz; radius-excluded
        // have d^2 > R2CHK; strictly-inside 9th => candidate top-9 == exact top-9.
        ok = (lasti != 0x7fffffff) && (__fmul_rn(d8, d8) < R2CHK);
    }
    if (!ok) {   // exact full scan (deterministic, identical arithmetic)
        float ldv = f_inf(); int liv = 0x7fffffff;
        for (int b = 0; b < N_; b += 32) {
            int idx = b + lane; bool v = idx < N_;
            float2 p = pb2[2 * (v ? idx : 0)];
            float dx = __fsub_rn(qg.x, p.x), dy = __fsub_rn(qg.y, p.y);
            float de = __fsqrt_rn(__fadd_rn(__fmul_rn(dx, dx), __fmul_rn(dy, dy)));
            insert_batch(de, idx, v, ldv, liv, lane);
        }
        myidx = liv;   // lanes 0..8 hold ranks 0..8
    }

    // ---- epilogue: lanes 0..8 in parallel, exact rn ops ----
    float ghw = __fmul_rn(0.5f, qg.z), ghh = __fmul_rn(0.5f, qg.w);
    float gx1 = __fsub_rn(qg.x, ghw), gy1 = __fsub_rn(qg.y, ghh);
    float gx2 = __fadd_rn(qg.x, ghw), gy2 = __fadd_rn(qg.y, ghh);
    float area_g = __fmul_rn(__fsub_rn(gx2, gx1), __fsub_rn(gy2, gy1));

    float iou = 0.0f, pcx = 0.0f, pcy = 0.0f;
    if (lane < KK) {
        float4 p = pb[myidx];
        pcx = p.x; pcy = p.y;
        float hw = __fmul_rn(0.5f, p.z), hh = __fmul_rn(0.5f, p.w);
        float bx1 = __fsub_rn(p.x, hw), by1 = __fsub_rn(p.y, hh);
        float bx2 = __fadd_rn(p.x, hw), by2 = __fadd_rn(p.y, hh);
        float ltx = fmaxf(gx1, bx1), lty = fmaxf(gy1, by1);
        float rbx = fminf(gx2, bx2), rby = fminf(gy2, by2);
        float wd = fmaxf(__fsub_rn(rbx, ltx), 0.0f);
        float ht = fmaxf(__fsub_rn(rby, lty), 0.0f);
        float inter = __fmul_rn(wd, ht);
        float area_b = __fmul_rn(__fsub_rn(bx2, bx1), __fsub_rn(by2, by1));
        float den = __fsub_rn(__fadd_rn(area_g, area_b), inter);
        iou = __fdiv_rn(inter, den);
    }
    float iouk[KK];
#pragma unroll
    for (int k = 0; k < KK; k++) iouk[k] = __shfl_sync(FULL, iou, k);
    float s = 0.0f;
#pragma unroll
    for (int k = 0; k < KK; k++) s = __fadd_rn(s, iouk[k]);
    float mean = __fdiv_rn(s, 9.0f);
    float vv = 0.0f;
#pragma unroll
    for (int k = 0; k < KK; k++) {
        float cdev = __fsub_rn(iouk[k], mean);
        vv = __fadd_rn(vv, __fmul_rn(cdev, cdev));
    }
    float thr = __fadd_rn(mean, __fsqrt_rn(__fdiv_rn(vv, 8.0f)));

    if (lane < KK) {
        bool inside = (gx1 <= pcx) && (pcx <= gx2) && (gy1 <= pcy) && (pcy <= gy2);
        bool msk = (iou >= thr) && inside;
        const size_t S = (size_t)B_ * G_ * KK;
        const size_t base = ((size_t)img * G_ + g) * KK + lane;
        out[base]         = msk ? (float)myidx : -1.0f;
        out[S + base]     = msk ? (float)g : -1.0f;
        out[2 * S + base] = msk ? 1.0f : 0.0f;
        out[3 * S + base] = iou;
    }
}

extern "C" void kernel_launch(void* const* d_in, const int* in_sizes, int n_in,
                              void* d_out, int out_size) {
    const float* pred = (const float*)d_in[0];  // [16,30000,4]
    const float* gt   = (const float*)d_in[1];  // [16,64,4]
    float* out = (float*)d_out;
    atss_compact<<<B_ * 16, NTHR>>>(pred, gt);            // 256 blocks
    atss_assign<<<(B_ * G_) / 4, 128>>>(pred, gt, out);   // 256 blocks
}